// round 8
// baseline (speedup 1.0000x reference)
#include <cuda_runtime.h>

#define S_ 8
#define U_ 32
#define V_ 32
#define C_ 32
#define SU 256              // S_*U_
#define SV 256              // S_*V_
#define WSEG (S_*U_*V_)     // 8192 floats per segment
#define WS_STRIDE 514       // u64 per s-slice: 512 + 2 pad
#define NBLOCKS 296         // 2 per SM on 148 SMs

// Warp = 8 s x 4 vq. Thread computes 8 rows x 8 v. Per u: 2 LDS.128 of W
// (512B all-unique, 4-cyc floor) reused across 8 rows -> W-LDS cut 8x vs R6.
// Fences per u-chunk prevent ptxas hoist-spills (R4/R5 failure mode).
__global__ __launch_bounds__(256, 2)
void idxlin_kernel(const float* __restrict__ W,     // (C, S*U*V)
                   const float* __restrict__ X,     // (Z, S*U)
                   const int*   __restrict__ counts,
                   const float* __restrict__ coef,
                   float* __restrict__ out,         // (Z, S*V)
                   int Z)
{
    __shared__ __align__(16) unsigned long long w_sh[S_ * WS_STRIDE]; // 32.9 KB
    __shared__ int segStart[C_ + 1];

    const int tid = threadIdx.x;
    if (tid == 0) {
        int a = 0; segStart[0] = 0;
        #pragma unroll
        for (int c = 0; c < C_; ++c) { a += counts[c]; segStart[c + 1] = a; }
    }
    __syncthreads();

    const int lane = tid & 31;
    const int wid  = tid >> 5;      // 8 warps
    const int s    = lane & 7;
    const int vq   = lane >> 3;     // 0..3 -> v-group of 8

    const int rpb = (Z + NBLOCKS - 1) / NBLOCKS;
    const int lo  = blockIdx.x * rpb;
    const int hi  = min(lo + rpb, Z);
    if (lo >= Z) return;

    int seg = 0;
    while (seg < C_ - 1 && segStart[seg + 1] <= lo) seg++;

    int cur = lo;
    while (cur < hi) {
        const int segTop = (seg < C_ - 1) ? segStart[seg + 1] : Z;
        const int e = min(segTop, hi);

        // ---- stage premultiplied W[seg] into padded SMEM (coalesced) ----
        __syncthreads();
        {
            const float4* wg = reinterpret_cast<const float4*>(W + (size_t)seg * WSEG);
            #pragma unroll
            for (int k = 0; k < WSEG / 4 / 256; ++k) {
                const int idx4 = tid + 256 * k;
                float4 w = wg[idx4];
                const int ss  = idx4 >> 8;
                const int rem = idx4 & 255;
                const float c0 = coef[ss];
                w.x *= c0; w.y *= c0; w.z *= c0; w.w *= c0;
                *reinterpret_cast<float4*>(&w_sh[ss * WS_STRIDE + rem * 2]) = w;
            }
        }
        __syncthreads();

        // Per-u W chunk for this thread: 4 u64 at s-slice + u*16 + vq*4.
        const unsigned long long* wb = &w_sh[s * WS_STRIDE + vq * 4];

        // ---- row loop: each warp takes 8 consecutive rows ----
        for (int r0 = cur + wid * 8; r0 < e; r0 += 8 * 8) {
            const int rmax = e - 1 - r0;               // >= 0
            // Clamped row offsets (in float4 units of 64 per row) for loads.
            int ro0 = 0;
            int ro1 = (1 <= rmax ? 1 : rmax) * 64;
            int ro2 = (2 <= rmax ? 2 : rmax) * 64;
            int ro3 = (3 <= rmax ? 3 : rmax) * 64;
            int ro4 = (4 <= rmax ? 4 : rmax) * 64;
            int ro5 = (5 <= rmax ? 5 : rmax) * 64;
            int ro6 = (6 <= rmax ? 6 : rmax) * 64;
            int ro7 = (7 <= rmax ? 7 : rmax) * 64;

            const float4* xb = reinterpret_cast<const float4*>(
                X + (size_t)r0 * SU + s * U_);

            // 32 named accumulators: A<r><j>, j = v-pair 0..3 (8 v per row).
            unsigned long long A00=0,A01=0,A02=0,A03=0, A10=0,A11=0,A12=0,A13=0,
                               A20=0,A21=0,A22=0,A23=0, A30=0,A31=0,A32=0,A33=0,
                               A40=0,A41=0,A42=0,A43=0, A50=0,A51=0,A52=0,A53=0,
                               A60=0,A61=0,A62=0,A63=0, A70=0,A71=0,A72=0,A73=0;

#define FMA2(acc, xx, ww) \
    asm("fma.rn.f32x2 %0, %1, %2, %0;" : "+l"(acc) : "l"(xx), "l"(ww));
#define ROW_FMA(Ar0, Ar1, Ar2, Ar3, xs) {                                      \
    unsigned long long xx;                                                     \
    asm("mov.b64 %0, {%1, %1};" : "=l"(xx) : "f"(xs));                         \
    FMA2(Ar0, xx, w01.x) FMA2(Ar1, xx, w01.y)                                  \
    FMA2(Ar2, xx, w23.x) FMA2(Ar3, xx, w23.y) }

// One u: 2 LDS.128 of W (4 u64), reused by all 8 rows (32 FFMA2).
#define DO_UC(uc)                                                              \
    {                                                                          \
        float4 x0 = xb[ro0 + (uc)], x1 = xb[ro1 + (uc)];                       \
        float4 x2 = xb[ro2 + (uc)], x3 = xb[ro3 + (uc)];                       \
        float4 x4 = xb[ro4 + (uc)], x5 = xb[ro5 + (uc)];                       \
        float4 x6 = xb[ro6 + (uc)], x7 = xb[ro7 + (uc)];                       \
        _Pragma("unroll")                                                      \
        for (int uu = 0; uu < 4; ++uu) {                                       \
            const int u = (uc) * 4 + uu;                                       \
            const ulonglong2* wp = reinterpret_cast<const ulonglong2*>(        \
                wb + u * 16);                                                  \
            ulonglong2 w01 = wp[0];                                            \
            ulonglong2 w23 = wp[1];                                            \
            float xs0, xs1, xs2, xs3, xs4, xs5, xs6, xs7;                      \
            switch (uu) {                                                      \
              case 0: xs0=x0.x; xs1=x1.x; xs2=x2.x; xs3=x3.x;                  \
                      xs4=x4.x; xs5=x5.x; xs6=x6.x; xs7=x7.x; break;           \
              case 1: xs0=x0.y; xs1=x1.y; xs2=x2.y; xs3=x3.y;                  \
                      xs4=x4.y; xs5=x5.y; xs6=x6.y; xs7=x7.y; break;           \
              case 2: xs0=x0.z; xs1=x1.z; xs2=x2.z; xs3=x3.z;                  \
                      xs4=x4.z; xs5=x5.z; xs6=x6.z; xs7=x7.z; break;           \
              default:xs0=x0.w; xs1=x1.w; xs2=x2.w; xs3=x3.w;                  \
                      xs4=x4.w; xs5=x5.w; xs6=x6.w; xs7=x7.w; break;           \
            }                                                                  \
            ROW_FMA(A00,A01,A02,A03, xs0) ROW_FMA(A10,A11,A12,A13, xs1)        \
            ROW_FMA(A20,A21,A22,A23, xs2) ROW_FMA(A30,A31,A32,A33, xs3)        \
            ROW_FMA(A40,A41,A42,A43, xs4) ROW_FMA(A50,A51,A52,A53, xs5)        \
            ROW_FMA(A60,A61,A62,A63, xs6) ROW_FMA(A70,A71,A72,A73, xs7)        \
        }                                                                      \
        asm volatile("" ::: "memory");  /* scheduling fence: no hoist-spill */ \
    }

            DO_UC(0) DO_UC(1) DO_UC(2) DO_UC(3)
            DO_UC(4) DO_UC(5) DO_UC(6) DO_UC(7)
#undef DO_UC
#undef ROW_FMA
#undef FMA2

            // Stores: out[r][s*32 + vq*8 + 0..7] as two float4 per row.
            float4* ob = reinterpret_cast<float4*>(
                out + (size_t)r0 * SV + s * V_ + vq * 8);
            float2 pa, pb;
#define STORE_ROW(rr, Ar0, Ar1, Ar2, Ar3)                                      \
    if (rr <= rmax) {                                                          \
        pa = *reinterpret_cast<float2*>(&Ar0);                                 \
        pb = *reinterpret_cast<float2*>(&Ar1);                                 \
        ob[rr * 64 + 0] = make_float4(pa.x, pa.y, pb.x, pb.y);                 \
        pa = *reinterpret_cast<float2*>(&Ar2);                                 \
        pb = *reinterpret_cast<float2*>(&Ar3);                                 \
        ob[rr * 64 + 1] = make_float4(pa.x, pa.y, pb.x, pb.y);                 \
    }
            STORE_ROW(0, A00,A01,A02,A03) STORE_ROW(1, A10,A11,A12,A13)
            STORE_ROW(2, A20,A21,A22,A23) STORE_ROW(3, A30,A31,A32,A33)
            STORE_ROW(4, A40,A41,A42,A43) STORE_ROW(5, A50,A51,A52,A53)
            STORE_ROW(6, A60,A61,A62,A63) STORE_ROW(7, A70,A71,A72,A73)
#undef STORE_ROW
        }

        cur = e;
        seg++;
        if (seg >= C_ && cur < hi) break;  // safety if counts undersum
    }
}

extern "C" void kernel_launch(void* const* d_in, const int* in_sizes, int n_in,
                              void* d_out, int out_size) {
    const float* W      = (const float*)d_in[0];   // input1 (C, S*U*V)
    const float* X      = (const float*)d_in[1];   // input2 (Z, S*U)
    const int*   counts = (const int*)d_in[2];
    const float* coef   = (const float*)d_in[3];
    float* out = (float*)d_out;

    int Z = in_sizes[1] / SU;
    idxlin_kernel<<<NBLOCKS, 256>>>(W, X, counts, coef, out, Z);
}

// round 9
// speedup vs baseline: 1.0412x; 1.0412x over previous
#include <cuda_runtime.h>

#define S_ 8
#define U_ 32
#define V_ 32
#define C_ 32
#define SU 256              // S_*U_
#define SV 256              // S_*V_
#define WSEG (S_*U_*V_)     // 8192 floats per segment
#define WS_STRIDE 514       // u64 per s-slice: 512 + 2 pad -> 16B-quad banks 4s+8vq
#define NBLOCKS 444         // 3 per SM on 148 SMs

// 128-thr blocks, 3/SM -> 170-reg ceiling: room for 64-reg accumulator file
// without spills (R4-R7 failure mode: acc spills at the 128-reg cap).
// Warp = 8 s x 4 vq; thread computes 8 rows x 8 v. Per u: 2 LDS.128 of W
// (512B all-unique, 4-cyc floor) reused across 8 rows.
__global__ __launch_bounds__(128, 3)
void idxlin_kernel(const float* __restrict__ W,     // (C, S*U*V)
                   const float* __restrict__ X,     // (Z, S*U)
                   const int*   __restrict__ counts,
                   const float* __restrict__ coef,
                   float* __restrict__ out,         // (Z, S*V)
                   int Z)
{
    __shared__ __align__(16) unsigned long long w_sh[S_ * WS_STRIDE]; // 32.9 KB
    __shared__ int segStart[C_ + 1];

    const int tid = threadIdx.x;
    if (tid == 0) {
        int a = 0; segStart[0] = 0;
        #pragma unroll
        for (int c = 0; c < C_; ++c) { a += counts[c]; segStart[c + 1] = a; }
    }
    __syncthreads();

    const int lane = tid & 31;
    const int wid  = tid >> 5;      // 4 warps
    const int s    = lane & 7;
    const int vq   = lane >> 3;     // 0..3 -> v-group of 8

    const int rpb = (Z + NBLOCKS - 1) / NBLOCKS;
    const int lo  = blockIdx.x * rpb;
    const int hi  = min(lo + rpb, Z);
    if (lo >= Z) return;

    int seg = 0;
    while (seg < C_ - 1 && segStart[seg + 1] <= lo) seg++;

    int cur = lo;
    while (cur < hi) {
        const int segTop = (seg < C_ - 1) ? segStart[seg + 1] : Z;
        const int e = min(segTop, hi);

        // ---- stage premultiplied W[seg] into padded SMEM (coalesced) ----
        __syncthreads();
        {
            const float4* wg = reinterpret_cast<const float4*>(W + (size_t)seg * WSEG);
            #pragma unroll
            for (int k = 0; k < WSEG / 4 / 128; ++k) {      // 16 iters
                const int idx4 = tid + 128 * k;
                float4 w = wg[idx4];
                const int ss  = idx4 >> 8;
                const int rem = idx4 & 255;
                const float c0 = coef[ss];
                w.x *= c0; w.y *= c0; w.z *= c0; w.w *= c0;
                *reinterpret_cast<float4*>(&w_sh[ss * WS_STRIDE + rem * 2]) = w;
            }
        }
        __syncthreads();

        // This thread's W view: s-slice + its vq 4-u64 chunk; u-stride = 8 u2.
        const ulonglong2* wp = reinterpret_cast<const ulonglong2*>(
            &w_sh[s * WS_STRIDE + vq * 4]);

        // ---- row loop: each warp takes 8 consecutive rows ----
        for (int r0 = cur + wid * 8; r0 < e; r0 += 4 * 8) {
            const int rmax = e - 1 - r0;               // >= 0
            int ro1 = (1 <= rmax ? 1 : rmax) * 64;
            int ro2 = (2 <= rmax ? 2 : rmax) * 64;
            int ro3 = (3 <= rmax ? 3 : rmax) * 64;
            int ro4 = (4 <= rmax ? 4 : rmax) * 64;
            int ro5 = (5 <= rmax ? 5 : rmax) * 64;
            int ro6 = (6 <= rmax ? 6 : rmax) * 64;
            int ro7 = (7 <= rmax ? 7 : rmax) * 64;

            const float4* xb = reinterpret_cast<const float4*>(
                X + (size_t)r0 * SU + s * U_);

            unsigned long long A00=0,A01=0,A02=0,A03=0, A10=0,A11=0,A12=0,A13=0,
                               A20=0,A21=0,A22=0,A23=0, A30=0,A31=0,A32=0,A33=0,
                               A40=0,A41=0,A42=0,A43=0, A50=0,A51=0,A52=0,A53=0,
                               A60=0,A61=0,A62=0,A63=0, A70=0,A71=0,A72=0,A73=0;

#define FMA2(acc, xx, ww) \
    asm("fma.rn.f32x2 %0, %1, %2, %0;" : "+l"(acc) : "l"(xx), "l"(ww));
// One row within a 4-u chunk: 1 LDG.128 of x, 16 FFMA2 against 8 held w-u2s.
#define DO_ROW(B0,B1,B2,B3, roff)                                              \
    {   float4 xq = xb[(roff) + uc];                                           \
        unsigned long long xx;                                                 \
        asm("mov.b64 %0, {%1, %1};" : "=l"(xx) : "f"(xq.x));                   \
        FMA2(B0, xx, wA.x) FMA2(B1, xx, wA.y) FMA2(B2, xx, wB.x) FMA2(B3, xx, wB.y) \
        asm("mov.b64 %0, {%1, %1};" : "=l"(xx) : "f"(xq.y));                   \
        FMA2(B0, xx, wC.x) FMA2(B1, xx, wC.y) FMA2(B2, xx, wD.x) FMA2(B3, xx, wD.y) \
        asm("mov.b64 %0, {%1, %1};" : "=l"(xx) : "f"(xq.z));                   \
        FMA2(B0, xx, wE.x) FMA2(B1, xx, wE.y) FMA2(B2, xx, wF.x) FMA2(B3, xx, wF.y) \
        asm("mov.b64 %0, {%1, %1};" : "=l"(xx) : "f"(xq.w));                   \
        FMA2(B0, xx, wG.x) FMA2(B1, xx, wG.y) FMA2(B2, xx, wH.x) FMA2(B3, xx, wH.y) \
    }

            #pragma unroll
            for (int uc = 0; uc < 8; ++uc) {
                // W for the 4 u's of this chunk: 8 LDS.128, held in regs.
                const ulonglong2* wc = wp + uc * 32;     // u-stride 8 u2
                ulonglong2 wA = wc[0],  wB = wc[1];      // u = 4*uc
                ulonglong2 wC = wc[8],  wD = wc[9];      // u = 4*uc+1
                ulonglong2 wE = wc[16], wF = wc[17];     // u = 4*uc+2
                ulonglong2 wG = wc[24], wH = wc[25];     // u = 4*uc+3
                DO_ROW(A00,A01,A02,A03, 0)
                DO_ROW(A10,A11,A12,A13, ro1)
                DO_ROW(A20,A21,A22,A23, ro2)
                DO_ROW(A30,A31,A32,A33, ro3)
                DO_ROW(A40,A41,A42,A43, ro4)
                DO_ROW(A50,A51,A52,A53, ro5)
                DO_ROW(A60,A61,A62,A63, ro6)
                DO_ROW(A70,A71,A72,A73, ro7)
                asm volatile("" ::: "memory");  // fence: cap the hoist window
            }
#undef DO_ROW
#undef FMA2

            // Stores: out[r][s*32 + vq*8 + 0..7] as two float4 per row.
            float4* ob = reinterpret_cast<float4*>(
                out + (size_t)r0 * SV + s * V_ + vq * 8);
            float2 pa, pb;
#define STORE_ROW(rr, B0,B1,B2,B3)                                             \
    if (rr <= rmax) {                                                          \
        pa = *reinterpret_cast<float2*>(&B0);                                  \
        pb = *reinterpret_cast<float2*>(&B1);                                  \
        ob[rr * 64 + 0] = make_float4(pa.x, pa.y, pb.x, pb.y);                 \
        pa = *reinterpret_cast<float2*>(&B2);                                  \
        pb = *reinterpret_cast<float2*>(&B3);                                  \
        ob[rr * 64 + 1] = make_float4(pa.x, pa.y, pb.x, pb.y);                 \
    }
            STORE_ROW(0, A00,A01,A02,A03) STORE_ROW(1, A10,A11,A12,A13)
            STORE_ROW(2, A20,A21,A22,A23) STORE_ROW(3, A30,A31,A32,A33)
            STORE_ROW(4, A40,A41,A42,A43) STORE_ROW(5, A50,A51,A52,A53)
            STORE_ROW(6, A60,A61,A62,A63) STORE_ROW(7, A70,A71,A72,A73)
#undef STORE_ROW
        }

        cur = e;
        seg++;
        if (seg >= C_ && cur < hi) break;  // safety if counts undersum
    }
}

extern "C" void kernel_launch(void* const* d_in, const int* in_sizes, int n_in,
                              void* d_out, int out_size) {
    const float* W      = (const float*)d_in[0];   // input1 (C, S*U*V)
    const float* X      = (const float*)d_in[1];   // input2 (Z, S*U)
    const int*   counts = (const int*)d_in[2];
    const float* coef   = (const float*)d_in[3];
    float* out = (float*)d_out;

    int Z = in_sizes[1] / SU;
    idxlin_kernel<<<NBLOCKS, 128>>>(W, X, counts, coef, out, Z);
}

// round 13
// speedup vs baseline: 1.7607x; 1.6911x over previous
#include <cuda_runtime.h>

#define S_ 8
#define U_ 32
#define V_ 32
#define C_ 32
#define SU 256              // S_*U_
#define SV 256              // S_*V_
#define WSEG (S_*U_*V_)     // 8192 floats per segment
#define WS_STRIDE 514       // u64 per s-slice: 512 + 2 pad
#define XW_U64 1024         // per-warp x buffer: 8 KB = 1024 u64 = 512 float4
#define NBLOCKS 444         // 3 per SM on 148 SMs
#define SMEM_BYTES ((S_ * WS_STRIDE + 4 * XW_U64) * 8)   // 65,664 B

// Warp = 8 s x 4 vq; thread computes 8 rows x 8 v. W premultiplied in SMEM
// (2 LDS.128/u, reused across 8 rows). x staged per-warp into swizzled SMEM so
// the compute loop has NO long-latency loads -> ptxas stops hoist-spilling the
// 64-reg accumulator file (R4-R8 failure mode).
__global__ __launch_bounds__(128, 3)
void idxlin_kernel(const float* __restrict__ W,     // (C, S*U*V)
                   const float* __restrict__ X,     // (Z, S*U)
                   const int*   __restrict__ counts,
                   const float* __restrict__ coef,
                   float* __restrict__ out,         // (Z, S*V)
                   int Z)
{
    extern __shared__ __align__(16) unsigned long long dynsm[];
    unsigned long long* w_sh = dynsm;                       // 8*514 u64
    __shared__ int segStart[C_ + 1];

    const int tid = threadIdx.x;
    if (tid == 0) {
        int a = 0; segStart[0] = 0;
        #pragma unroll
        for (int c = 0; c < C_; ++c) { a += counts[c]; segStart[c + 1] = a; }
    }
    __syncthreads();

    const int lane = tid & 31;
    const int wid  = tid >> 5;      // 4 warps
    const int s    = lane & 7;
    const int vq   = lane >> 3;     // 0..3 -> v-group of 8

    float4* xw = reinterpret_cast<float4*>(dynsm + S_ * WS_STRIDE + wid * XW_U64);

    const int rpb = (Z + NBLOCKS - 1) / NBLOCKS;
    const int lo  = blockIdx.x * rpb;
    const int hi  = min(lo + rpb, Z);
    if (lo >= Z) return;

    int seg = 0;
    while (seg < C_ - 1 && segStart[seg + 1] <= lo) seg++;

    int cur = lo;
    while (cur < hi) {
        const int segTop = (seg < C_ - 1) ? segStart[seg + 1] : Z;
        const int e = min(segTop, hi);

        // ---- stage premultiplied W[seg] into padded SMEM (coalesced) ----
        __syncthreads();
        {
            const float4* wg = reinterpret_cast<const float4*>(W + (size_t)seg * WSEG);
            #pragma unroll
            for (int k = 0; k < WSEG / 4 / 128; ++k) {      // 16 iters
                const int idx4 = tid + 128 * k;
                float4 w = wg[idx4];
                const int ss  = idx4 >> 8;
                const int rem = idx4 & 255;
                const float c0 = coef[ss];
                w.x *= c0; w.y *= c0; w.z *= c0; w.w *= c0;
                *reinterpret_cast<float4*>(&w_sh[ss * WS_STRIDE + rem * 2]) = w;
            }
        }
        __syncthreads();

        // This thread's W view: s-slice + vq chunk; u-stride = 8 ulonglong2.
        const ulonglong2* wp = reinterpret_cast<const ulonglong2*>(
            &w_sh[s * WS_STRIDE + vq * 4]);

        // ---- row loop: each warp takes 8 consecutive rows ----
        for (int r0 = cur + wid * 8; r0 < e; r0 += 4 * 8) {
            const int rmax = min(7, e - 1 - r0);

            // ---- stage 8 rows of x into per-warp swizzled SMEM ----
            __syncwarp();   // prior compute done reading xw
            {
                const float4* Xg = reinterpret_cast<const float4*>(X)
                                   + (size_t)r0 * 64;
                #pragma unroll
                for (int k = 0; k < 16; ++k) {
                    const int g   = k * 32 + lane;      // linear float4 idx
                    const int row = g >> 6;
                    const int su4 = g & 63;
                    const int crow = row <= rmax ? row : rmax;
                    float4 v = Xg[(size_t)crow * 64 + su4];
                    // swizzle: low3 ^= s  (s = (g>>3)&7 since 8|row*64)
                    const int F = (g & ~7) | ((g & 7) ^ ((g >> 3) & 7));
                    xw[F] = v;
                }
            }
            __syncwarp();

            const float4* xr = xw + 8 * s;   // this thread's s-chunk base

            unsigned long long A00=0,A01=0,A02=0,A03=0, A10=0,A11=0,A12=0,A13=0,
                               A20=0,A21=0,A22=0,A23=0, A30=0,A31=0,A32=0,A33=0,
                               A40=0,A41=0,A42=0,A43=0, A50=0,A51=0,A52=0,A53=0,
                               A60=0,A61=0,A62=0,A63=0, A70=0,A71=0,A72=0,A73=0;

#define FMA2(acc, xx, ww) \
    asm("fma.rn.f32x2 %0, %1, %2, %0;" : "+l"(acc) : "l"(xx), "l"(ww));
// One row in a 4-u chunk: 1 broadcast LDS.128 of x, 16 FFMA2 vs held w.
#define DO_ROW(B0,B1,B2,B3, rr)                                                \
    {   float4 xq = xr[(rr) * 64 + xo];                                        \
        unsigned long long xx;                                                 \
        asm("mov.b64 %0, {%1, %1};" : "=l"(xx) : "f"(xq.x));                   \
        FMA2(B0, xx, wA.x) FMA2(B1, xx, wA.y) FMA2(B2, xx, wB.x) FMA2(B3, xx, wB.y) \
        asm("mov.b64 %0, {%1, %1};" : "=l"(xx) : "f"(xq.y));                   \
        FMA2(B0, xx, wC.x) FMA2(B1, xx, wC.y) FMA2(B2, xx, wD.x) FMA2(B3, xx, wD.y) \
        asm("mov.b64 %0, {%1, %1};" : "=l"(xx) : "f"(xq.z));                   \
        FMA2(B0, xx, wE.x) FMA2(B1, xx, wE.y) FMA2(B2, xx, wF.x) FMA2(B3, xx, wF.y) \
        asm("mov.b64 %0, {%1, %1};" : "=l"(xx) : "f"(xq.w));                   \
        FMA2(B0, xx, wG.x) FMA2(B1, xx, wG.y) FMA2(B2, xx, wH.x) FMA2(B3, xx, wH.y) \
    }

            #pragma unroll
            for (int uc = 0; uc < 8; ++uc) {
                const ulonglong2* wc = wp + uc * 32;     // u-stride 8 u2
                ulonglong2 wA = wc[0],  wB = wc[1];      // u = 4*uc
                ulonglong2 wC = wc[8],  wD = wc[9];      // u = 4*uc+1
                ulonglong2 wE = wc[16], wF = wc[17];     // u = 4*uc+2
                ulonglong2 wG = wc[24], wH = wc[25];     // u = 4*uc+3
                const int xo = uc ^ s;                   // swizzled chunk idx
                DO_ROW(A00,A01,A02,A03, 0)
                DO_ROW(A10,A11,A12,A13, 1)
                DO_ROW(A20,A21,A22,A23, 2)
                DO_ROW(A30,A31,A32,A33, 3)
                DO_ROW(A40,A41,A42,A43, 4)
                DO_ROW(A50,A51,A52,A53, 5)
                DO_ROW(A60,A61,A62,A63, 6)
                DO_ROW(A70,A71,A72,A73, 7)
                asm volatile("" ::: "memory");  // cap the scheduling window
            }
#undef DO_ROW
#undef FMA2

            // Stores: out[r][s*32 + vq*8 + 0..7], two float4 per row.
            float4* ob = reinterpret_cast<float4*>(
                out + (size_t)r0 * SV + s * V_ + vq * 8);
            float2 pa, pb;
#define STORE_ROW(rr, B0,B1,B2,B3)                                             \
    if (rr <= rmax) {                                                          \
        pa = *reinterpret_cast<float2*>(&B0);                                  \
        pb = *reinterpret_cast<float2*>(&B1);                                  \
        ob[rr * 64 + 0] = make_float4(pa.x, pa.y, pb.x, pb.y);                 \
        pa = *reinterpret_cast<float2*>(&B2);                                  \
        pb = *reinterpret_cast<float2*>(&B3);                                  \
        ob[rr * 64 + 1] = make_float4(pa.x, pa.y, pb.x, pb.y);                 \
    }
            STORE_ROW(0, A00,A01,A02,A03) STORE_ROW(1, A10,A11,A12,A13)
            STORE_ROW(2, A20,A21,A22,A23) STORE_ROW(3, A30,A31,A32,A33)
            STORE_ROW(4, A40,A41,A42,A43) STORE_ROW(5, A50,A51,A52,A53)
            STORE_ROW(6, A60,A61,A62,A63) STORE_ROW(7, A70,A71,A72,A73)
#undef STORE_ROW
        }

        cur = e;
        seg++;
        if (seg >= C_ && cur < hi) break;  // safety if counts undersum
    }
}

extern "C" void kernel_launch(void* const* d_in, const int* in_sizes, int n_in,
                              void* d_out, int out_size) {
    const float* W      = (const float*)d_in[0];   // input1 (C, S*U*V)
    const float* X      = (const float*)d_in[1];   // input2 (Z, S*U)
    const int*   counts = (const int*)d_in[2];
    const float* coef   = (const float*)d_in[3];
    float* out = (float*)d_out;

    cudaFuncSetAttribute(idxlin_kernel,
                         cudaFuncAttributeMaxDynamicSharedMemorySize,
                         SMEM_BYTES);

    int Z = in_sizes[1] / SU;
    idxlin_kernel<<<NBLOCKS, 128, SMEM_BYTES>>>(W, X, counts, coef, out, Z);
}